// round 13
// baseline (speedup 1.0000x reference)
#include <cuda_runtime.h>

#define NN 784
#define GRID 28
#define MAXB 64
#define MAXD2 1459   // d2 in [0, 27^2+27^2=1458]

// Scratch (device globals — no allocations allowed)
__device__ unsigned g_packed[NN * NN];           // [i][rank] -> (d2<<16)|idx
__device__ float g_fvals[2 * MAXB * NN];         // [g][m][i] dtm values
__device__ float g_feats[MAXB * 320];            // landscape features per image

__constant__ int c_dxs[8] = {-1, 1, 0, 0, -1, -1, 1, 1};
__constant__ int c_dys[8] = {0, 0, -1, 1, -1, 1, -1, 1};
__constant__ int c_off[8] = {-28, 28, -1, 1, -29, -27, 27, 29};

// ---------------------------------------------------------------------------
// Kernel A: stable argsort of squared grid distances per point (counting sort)
// writes packed (d2<<16)|idx
// ---------------------------------------------------------------------------
__global__ void build_sort_table_kernel() {
    int i = blockIdx.x;
    int xi = i / GRID, yi = i % GRID;
    __shared__ unsigned int hist[MAXD2];
    __shared__ unsigned short d2a[NN];
    __shared__ unsigned int wsum[8];
    int tid = threadIdx.x;
    int lane = tid & 31, warp = tid >> 5;

    for (int t = tid; t < MAXD2; t += 256) hist[t] = 0u;
    __syncthreads();
    for (int j = tid; j < NN; j += 256) {
        int dx = j / GRID - xi, dy = j % GRID - yi;
        int d2 = dx * dx + dy * dy;
        d2a[j] = (unsigned short)d2;
        atomicAdd(&hist[d2], 1u);
    }
    __syncthreads();

    // exclusive scan of hist[0..1458] (6 entries per thread, 256 threads)
    unsigned int lv[6];
    unsigned int s = 0u;
    int base = tid * 6;
#pragma unroll
    for (int c = 0; c < 6; c++) {
        unsigned int v = (base + c < MAXD2) ? hist[base + c] : 0u;
        lv[c] = s;
        s += v;
    }
    unsigned int inc = s;
#pragma unroll
    for (int off = 1; off < 32; off <<= 1) {
        unsigned int t = __shfl_up_sync(0xFFFFFFFFu, inc, off);
        if (lane >= off) inc += t;
    }
    if (lane == 31) wsum[warp] = inc;
    __syncthreads();
    if (tid == 0) {
        unsigned int a = 0u;
        for (int w = 0; w < 8; w++) { unsigned int t = wsum[w]; wsum[w] = a; a += t; }
    }
    __syncthreads();
    unsigned int off0 = wsum[warp] + (inc - s);
    __syncthreads();  // all reads of hist done before overwrite
#pragma unroll
    for (int c = 0; c < 6; c++)
        if (base + c < MAXD2) hist[base + c] = off0 + lv[c];
    __syncthreads();

    // Stable scatter: warps serialized in ascending-j order
    for (int gq = 0; gq < 25; gq++) {
        if (warp == (gq & 7)) {
            int j = gq * 32 + lane;
            bool valid = (j < NN);
            unsigned int key = valid ? (unsigned int)d2a[j] : 0xFFFFu;
            unsigned int mk = __match_any_sync(0xFFFFFFFFu, key);
            int leader = __ffs(mk) - 1;
            int pre = __popc(mk & ((1u << lane) - 1u));
            unsigned int b0 = 0u;
            if (lane == leader && valid) b0 = atomicAdd(&hist[key], (unsigned int)__popc(mk));
            b0 = __shfl_sync(0xFFFFFFFFu, b0, leader);
            if (valid) g_packed[i * NN + b0 + pre] = (key << 16) | (unsigned)j;
        }
        __syncthreads();
    }
}

// ---------------------------------------------------------------------------
// Kernel B: DTM, thread-per-point sequential scan, both m0 in one pass.
// Grid (B, 4): block y handles points {4*tid + y | tid < 196}.
// ---------------------------------------------------------------------------
__global__ void dtm_kernel(const float* __restrict__ x) {
    int m = blockIdx.x;
    __shared__ float img[NN];
    __shared__ float red[8];
    int tid = threadIdx.x;
    int lane = tid & 31, warp = tid >> 5;

    float ps = 0.f;
    for (int j = tid; j < NN; j += 256) {
        float v = x[m * NN + j];
        img[j] = v;
        ps += v;
    }
#pragma unroll
    for (int off = 16; off; off >>= 1) ps += __shfl_xor_sync(0xFFFFFFFFu, ps, off);
    if (lane == 0) red[warp] = ps;
    __syncthreads();
    float S = 0.f;
#pragma unroll
    for (int w = 0; w < 8; w++) S += red[w];
    float bound1 = 0.05f * S;
    float bound2 = 0.2f * S;

    int i = 4 * tid + blockIdx.y;
    if (tid < 196) {
        const uint4* row = (const uint4*)(g_packed + i * NN);
        float acc1 = 0.f, acc2 = 0.f, running = 0.f;
        for (int c4 = 0; c4 < NN / 4; c4++) {
            uint4 p = row[c4];
#define DTM_ELEM(pp) { unsigned _idx = (pp) & 0xFFFFu; float _fd2 = (float)((pp) >> 16); \
                       float _w = img[_idx]; float _cb = running; running = _cb + _w;   \
                       acc1 += fminf(fmaxf(bound1 - _cb, 0.f), _w) * _fd2;              \
                       acc2 += fminf(fmaxf(bound2 - _cb, 0.f), _w) * _fd2; }
            DTM_ELEM(p.x); DTM_ELEM(p.y); DTM_ELEM(p.z); DTM_ELEM(p.w);
#undef DTM_ELEM
            if (running >= bound2) break;   // all further eff are exactly 0
        }
        g_fvals[(0 * MAXB + m) * NN + i] = sqrtf(acc1 / bound1);
        g_fvals[(1 * MAXB + m) * NN + i] = sqrtf(acc2 / bound2);
    }
}

// ---------------------------------------------------------------------------
// Kernel C: hybrid register/smem bitonic sort + batched union-find with
// PER-SUB single-root fast path and branchless slow path + fused landscape.
// Pairs stored at slot = loser root id (unique per run; zero-fill -> tent 0).
// ---------------------------------------------------------------------------
struct SmemC {
    unsigned long long keys[1024];
    float vals[NN];
    unsigned order32[NN + 4];        // (yj<<24)|(xj<<16)|j per rank
    unsigned par32[NN + 2];          // root: (birth_pos<<16)|root ; else low16=parent
                                     // [NN], [NN+1] = write-only dummy slots
    unsigned short pos_[NN];
    unsigned char nbm[NN + 4];       // per-rank eligible-neighbor bitmask (+pad)
    float2 spBD[NN + 1];             // (birth, death) per loser-root slot; [NN]=dummy
};

// one bitonic compare-exchange stage in registers (jj<=16), lane-local via shfl
__device__ __forceinline__ void reg_stage(unsigned long long v[4], int w, int lane,
                                          int k, int jj) {
#pragma unroll
    for (int q = 0; q < 4; q++) {
        int i = (w << 7) + (q << 5) + lane;
        unsigned long long p = __shfl_xor_sync(0xFFFFFFFFu, v[q], jj);
        bool up = ((i & k) == 0);
        bool lowidx = ((lane & jj) == 0);
        bool keepmin = (up == lowidx);
        bool less = (v[q] < p);
        v[q] = (less == keepmin) ? v[q] : p;
    }
}

template <int DIR>
__device__ __forceinline__ void pairs_body(SmemC* s, int g, int m) {
    int tid = threadIdx.x;
    int lane = tid & 31, warp = tid >> 5;
    const unsigned EMASK = DIR ? 0xFFu : 0x0Fu;
    const unsigned INV = 0xFFFFFFFFu;
    const unsigned FULL = 0xFFFFFFFFu;

    for (int j = tid; j < NN; j += 256) {
        float v = g_fvals[(g * MAXB + m) * NN + j];
        s->vals[j] = v;
        float kf = DIR ? -v : v;  // dir1: superlevel via -x
        unsigned int u = __float_as_uint(kf);
        u = (u & 0x80000000u) ? ~u : (u | 0x80000000u);  // sortable transform
        s->keys[j] = ((unsigned long long)u << 32) | (unsigned int)j;  // stable ties by j
        s->spBD[j] = make_float2(0.f, 0.f);
    }
    for (int j = NN + tid; j < 1024; j += 256) s->keys[j] = ~0ULL;
    __syncthreads();

    // ---- hybrid bitonic sort of 1024 u64 keys ----
    // register layout: lane handles elements (w*128 + q*32 + lane), q=0..3
    {
        unsigned long long v[4];
#pragma unroll
        for (int q = 0; q < 4; q++) v[q] = s->keys[(warp << 7) + (q << 5) + lane];
        // k = 2..32 entirely in registers (15 stages, no barriers)
#pragma unroll
        for (int k = 2; k <= 32; k <<= 1)
            for (int jj = k >> 1; jj >= 1; jj >>= 1)
                reg_stage(v, warp, lane, k, jj);
#pragma unroll
        for (int q = 0; q < 4; q++) s->keys[(warp << 7) + (q << 5) + lane] = v[q];
        __syncthreads();

        for (int k = 64; k <= 1024; k <<= 1) {
            for (int jj = k >> 1; jj >= 32; jj >>= 1) {
                for (int i = tid; i < 1024; i += 256) {
                    int ixj = i ^ jj;
                    if (ixj > i) {
                        unsigned long long a = s->keys[i], b = s->keys[ixj];
                        bool up = ((i & k) == 0);
                        if ((a > b) == up) { s->keys[i] = b; s->keys[ixj] = a; }
                    }
                }
                __syncthreads();
            }
            // register tail: jj = 16..1
#pragma unroll
            for (int q = 0; q < 4; q++) v[q] = s->keys[(warp << 7) + (q << 5) + lane];
            for (int jj = 16; jj >= 1; jj >>= 1)
                reg_stage(v, warp, lane, k, jj);
#pragma unroll
            for (int q = 0; q < 4; q++) s->keys[(warp << 7) + (q << 5) + lane] = v[q];
            __syncthreads();
        }
    }

    for (int r = tid; r < NN; r += 256) {
        int j = (int)(unsigned int)s->keys[r];
        int xj = j / GRID, yj = j % GRID;
        s->order32[r] = (unsigned)j | ((unsigned)xj << 16) | ((unsigned)yj << 24);
        s->pos_[j] = (unsigned short)r;
        s->par32[j] = ((unsigned)r << 16) | (unsigned)j;   // root: birth<<16 | self
    }
    if (tid < 4) {
        s->order32[NN + tid] = 0u;
        s->nbm[NN + tid] = 0;
    }
    __syncthreads();

    // precompute per-rank eligible-neighbor bitmask (pos[u] < r, in bounds)
    for (int r = tid; r < NN; r += 256) {
        unsigned o = s->order32[r];
        int v = (int)(o & 0xFFFFu);
        int xv = (int)((o >> 16) & 0xFFu), yv = (int)(o >> 24);
        unsigned mask = 0u;
#pragma unroll
        for (int l = 0; l < 8; l++) {
            int xu = xv + c_dxs[l], yu = yv + c_dys[l];
            if ((unsigned)xu < (unsigned)GRID && (unsigned)yu < (unsigned)GRID &&
                (int)s->pos_[v + c_off[l]] < r)
                mask |= 1u << l;
        }
        s->nbm[r] = (unsigned char)mask;
    }
    __syncthreads();

    // ---- batched union-find: warp 0. 4 vertices/step, 8 lanes each.
    // packed = (birth_pos<<16)|root; min packed wins; fresh vertex always loses.
    if (tid < 32) {
        volatile unsigned* par = s->par32;
        int sub = lane >> 3, sl = lane & 7;
        unsigned lmlt = (1u << lane) - 1u;
        unsigned submask = 0xFFu << (sub << 3);
        unsigned em = (unsigned)s->nbm[sub] & EMASK;
        unsigned ov = s->order32[sub];
        for (int base = 0; base < NN; base += 4) {
            // prefetch next batch's mask/vertex (independent of par state)
            unsigned em_n = (unsigned)s->nbm[base + 4 + sub] & EMASK;
            unsigned ov_n = s->order32[base + 4 + sub];

            // optimistic finds against pre-batch parent state
            unsigned cur = INV;
            if ((em >> sl) & 1u) {
                int xx = (int)(ov & 0xFFFFu) + c_off[sl];
                for (;;) {  // find, 2 levels/iter with path halving
                    unsigned p32 = par[xx];
                    int pl = (int)(p32 & 0xFFFFu);
                    if (pl == xx) { cur = p32; break; }
                    unsigned q32 = par[pl];
                    int ql = (int)(q32 & 0xFFFFu);
                    if (ql == pl) { cur = q32; break; }
                    par[xx] = q32;      // halve: xx -> grandparent
                    xx = ql;
                }
            }

            bool valid = (cur != INV);
            // PER-SUB single-root fast check: each sub's merge is then
            // {one pre-batch root} U {fresh vertex} -> root wins, no root dies,
            // only zero-persistence pairs. Cross-sub root sharing harmless.
            unsigned amin = __reduce_min_sync(submask, valid ? cur : INV);
            unsigned amax = __reduce_max_sync(submask, valid ? cur : 0u);
            bool okl = (amin > amax) ||
                       ((amin == amax) && ((amin >> 16) < (unsigned)base));
            if (__all_sync(FULL, okl)) {
                // all merges are fresh-vertex joins: no pairs, just joins (branchless)
                unsigned fa = valid ? (ov & 0xFFFFu) : (unsigned)NN;
                par[fa] = cur;   // sub-uniform value; benign race within sub
            } else {
                // ---- exact serial 4-substep fix-up, branchless stores ----
                unsigned pvall = ((unsigned)(base + sub) << 16) | (ov & 0xFFFFu);
                unsigned pv0 = __shfl_sync(FULL, pvall, 0);
                unsigned pv1 = __shfl_sync(FULL, pvall, 8);
                unsigned pv2 = __shfl_sync(FULL, pvall, 16);
                unsigned pv3 = __shfl_sync(FULL, pvall, 24);
                unsigned grp = __match_any_sync(FULL, cur);
#pragma unroll
                for (int j = 0; j < 4; j++) {
                    unsigned pvj = (j < 2) ? (j == 0 ? pv0 : pv1) : (j == 2 ? pv2 : pv3);
                    unsigned grp2 = (j == 0) ? grp : __match_any_sync(FULL, cur);
                    bool valid2 = (cur != INV);
                    bool inj = (sub == j);
                    unsigned wjj = __reduce_min_sync(FULL, (valid2 && inj) ? cur : INV);
                    bool anyv = (wjj != INV);
                    bool deadval = inj && valid2 && (cur != wjj);
                    unsigned dmask = __ballot_sync(FULL, deadval);
                    bool leader = deadval && ((grp2 & dmask & lmlt) == 0u);
                    // branchless stores via dummy slots (no BSSY/BSYNC)
                    unsigned slot = leader ? (cur & 0xFFFFu) : (unsigned)NN;
                    unsigned bp = deadval ? (cur >> 16) : 0u;
                    int lbv = (int)(s->order32[bp] & 0xFFFFu);
                    unsigned vj = pvj & 0xFFFFu;
                    float Bv, Dv;
                    if (DIR == 0) { Bv = s->vals[lbv]; Dv = s->vals[vj]; }
                    else          { Bv = s->vals[vj];  Dv = s->vals[lbv]; }
                    s->spBD[slot] = make_float2(Bv, Dv);
                    par[slot] = wjj;                       // loser root -> winner
                    unsigned fa = (anyv && lane == 0) ? vj : (unsigned)(NN + 1);
                    par[fa] = wjj;                         // fresh vertex joins winner
                    // stale fix (registers only)
                    if (sub > j && valid2) {
                        bool stale = ((grp2 & dmask) != 0u) || (anyv && cur == pvj);
                        if (stale) cur = wjj;
                    }
                }
            }
            __syncwarp();
            em = em_n;
            ov = ov_n;
        }
    }
    __syncthreads();

    // ---- fused landscape top-K: 32 t-values, warp per t ----
    int K = g ? 3 : 2;
    float start = g ? 1.0f : 0.0f;
    int fbase = m * 320 + (g ? 128 : 0);
    for (int ti = warp; ti < 32; ti += 8) {
        float t = start + 7.0f * (float)ti / 31.0f;
        float a0 = -1.f, a1 = -1.f, a2 = -1.f;
        for (int j = lane; j < NN; j += 32) {
            float2 bd = s->spBD[j];
            float tent = fmaxf(fminf(t - bd.x, bd.y - t), 0.f);
            if (tent > a2) {
                if (tent > a0)      { a2 = a1; a1 = a0; a0 = tent; }
                else if (tent > a1) { a2 = a1; a1 = tent; }
                else                { a2 = tent; }
            }
        }
        for (int kk = 0; kk < K; kk++) {
            float w = a0;
#pragma unroll
            for (int off = 16; off; off >>= 1) w = fmaxf(w, __shfl_xor_sync(0xFFFFFFFFu, w, off));
            unsigned bal = __ballot_sync(0xFFFFFFFFu, a0 == w);
            int src = __ffs(bal) - 1;
            if (lane == src) { a0 = a1; a1 = a2; a2 = -1.f; }
            if (lane == 0) g_feats[fbase + (DIR * K + kk) * 32 + ti] = w;
        }
    }
}

__global__ void pairs_kernel() {
    __shared__ SmemC smc;
    int task = blockIdx.x;
    int dir = task & 1;
    int g = (task >> 1) & 1;
    int m = task >> 2;
    if (dir == 0) pairs_body<0>(&smc, g, m);
    else          pairs_body<1>(&smc, g, m);
}

// ---------------------------------------------------------------------------
// Kernel D: tiny MLP. Block per image, 512 threads, warp-per-unit dots.
// ---------------------------------------------------------------------------
__global__ void mlp_kernel(const float* __restrict__ wg1, const float* __restrict__ bg1,
                           const float* __restrict__ wg2, const float* __restrict__ bg2,
                           const float* __restrict__ wfc, const float* __restrict__ bfc,
                           float* __restrict__ out) {
    int m = blockIdx.x;
    __shared__ float sx[64];
    int tid = threadIdx.x;
    int lane = tid & 31, w = tid >> 5;   // 16 warps
    const float* feats = g_feats + m * 320;

#pragma unroll
    for (int i = 0; i < 2; i++) {
        int u = w * 2 + i;
        float a = 0.f;
#pragma unroll
        for (int c = lane; c < 128; c += 32) a += feats[c] * wg1[u * 128 + c];
#pragma unroll
        for (int off = 16; off; off >>= 1) a += __shfl_xor_sync(0xFFFFFFFFu, a, off);
        if (lane == 0) sx[u] = fmaxf(a + bg1[u], 0.f);
    }
#pragma unroll
    for (int i = 0; i < 2; i++) {
        int u = w * 2 + i;
        float a = 0.f;
#pragma unroll
        for (int c = lane; c < 192; c += 32) a += feats[128 + c] * wg2[u * 192 + c];
#pragma unroll
        for (int off = 16; off; off >>= 1) a += __shfl_xor_sync(0xFFFFFFFFu, a, off);
        if (lane == 0) sx[32 + u] = fmaxf(a + bg2[u], 0.f);
    }
    __syncthreads();
    if (tid < 10) {
        float a = bfc[tid];
#pragma unroll
        for (int c = 0; c < 64; c++) a += sx[c] * wfc[tid * 64 + c];
        out[m * 10 + tid] = a;
    }
}

// ---------------------------------------------------------------------------
extern "C" void kernel_launch(void* const* d_in, const int* in_sizes, int n_in,
                              void* d_out, int out_size) {
    const float* x   = (const float*)d_in[0];
    const float* wg1 = (const float*)d_in[1];
    const float* bg1 = (const float*)d_in[2];
    const float* wg2 = (const float*)d_in[3];
    const float* bg2 = (const float*)d_in[4];
    const float* wfc = (const float*)d_in[5];
    const float* bfc = (const float*)d_in[6];
    float* out = (float*)d_out;
    int B = in_sizes[0] / NN;
    if (B > MAXB) B = MAXB;

    build_sort_table_kernel<<<NN, 256>>>();
    dtm_kernel<<<dim3(B, 4), 256>>>(x);
    pairs_kernel<<<B * 4, 256>>>();
    mlp_kernel<<<B, 512>>>(wg1, bg1, wg2, bg2, wfc, bfc, out);
}

// round 14
// speedup vs baseline: 1.5451x; 1.5451x over previous
#include <cuda_runtime.h>

#define NN 784
#define GRID 28
#define MAXB 64
#define MAXD2 1459   // d2 in [0, 27^2+27^2=1458]

// Scratch (device globals — no allocations allowed)
__device__ unsigned g_packed[NN * NN];           // [i][rank] -> (d2<<16)|idx
__device__ float g_fvals[2 * MAXB * NN];         // [g][m][i] dtm values
__device__ float g_feats[MAXB * 320];            // landscape features per image

__constant__ int c_dxs[8] = {-1, 1, 0, 0, -1, -1, 1, 1};
__constant__ int c_dys[8] = {0, 0, -1, 1, -1, 1, -1, 1};
__constant__ int c_off[8] = {-28, 28, -1, 1, -29, -27, 27, 29};

// ---------------------------------------------------------------------------
// Kernel A: stable argsort of squared grid distances per point (counting sort)
// writes packed (d2<<16)|idx
// ---------------------------------------------------------------------------
__global__ void build_sort_table_kernel() {
    int i = blockIdx.x;
    int xi = i / GRID, yi = i % GRID;
    __shared__ unsigned int hist[MAXD2];
    __shared__ unsigned short d2a[NN];
    __shared__ unsigned int wsum[8];
    int tid = threadIdx.x;
    int lane = tid & 31, warp = tid >> 5;

    for (int t = tid; t < MAXD2; t += 256) hist[t] = 0u;
    __syncthreads();
    for (int j = tid; j < NN; j += 256) {
        int dx = j / GRID - xi, dy = j % GRID - yi;
        int d2 = dx * dx + dy * dy;
        d2a[j] = (unsigned short)d2;
        atomicAdd(&hist[d2], 1u);
    }
    __syncthreads();

    // exclusive scan of hist[0..1458] (6 entries per thread, 256 threads)
    unsigned int lv[6];
    unsigned int s = 0u;
    int base = tid * 6;
#pragma unroll
    for (int c = 0; c < 6; c++) {
        unsigned int v = (base + c < MAXD2) ? hist[base + c] : 0u;
        lv[c] = s;
        s += v;
    }
    unsigned int inc = s;
#pragma unroll
    for (int off = 1; off < 32; off <<= 1) {
        unsigned int t = __shfl_up_sync(0xFFFFFFFFu, inc, off);
        if (lane >= off) inc += t;
    }
    if (lane == 31) wsum[warp] = inc;
    __syncthreads();
    if (tid == 0) {
        unsigned int a = 0u;
        for (int w = 0; w < 8; w++) { unsigned int t = wsum[w]; wsum[w] = a; a += t; }
    }
    __syncthreads();
    unsigned int off0 = wsum[warp] + (inc - s);
    __syncthreads();  // all reads of hist done before overwrite
#pragma unroll
    for (int c = 0; c < 6; c++)
        if (base + c < MAXD2) hist[base + c] = off0 + lv[c];
    __syncthreads();

    // Stable scatter: warps serialized in ascending-j order
    for (int gq = 0; gq < 25; gq++) {
        if (warp == (gq & 7)) {
            int j = gq * 32 + lane;
            bool valid = (j < NN);
            unsigned int key = valid ? (unsigned int)d2a[j] : 0xFFFFu;
            unsigned int mk = __match_any_sync(0xFFFFFFFFu, key);
            int leader = __ffs(mk) - 1;
            int pre = __popc(mk & ((1u << lane) - 1u));
            unsigned int b0 = 0u;
            if (lane == leader && valid) b0 = atomicAdd(&hist[key], (unsigned int)__popc(mk));
            b0 = __shfl_sync(0xFFFFFFFFu, b0, leader);
            if (valid) g_packed[i * NN + b0 + pre] = (key << 16) | (unsigned)j;
        }
        __syncthreads();
    }
}

// ---------------------------------------------------------------------------
// Kernel B: DTM, thread-per-point sequential scan, both m0 in one pass.
// Grid (B, 4): block y handles points {4*tid + y | tid < 196}.
// ---------------------------------------------------------------------------
__global__ void dtm_kernel(const float* __restrict__ x) {
    int m = blockIdx.x;
    __shared__ float img[NN];
    __shared__ float red[8];
    int tid = threadIdx.x;
    int lane = tid & 31, warp = tid >> 5;

    float ps = 0.f;
    for (int j = tid; j < NN; j += 256) {
        float v = x[m * NN + j];
        img[j] = v;
        ps += v;
    }
#pragma unroll
    for (int off = 16; off; off >>= 1) ps += __shfl_xor_sync(0xFFFFFFFFu, ps, off);
    if (lane == 0) red[warp] = ps;
    __syncthreads();
    float S = 0.f;
#pragma unroll
    for (int w = 0; w < 8; w++) S += red[w];
    float bound1 = 0.05f * S;
    float bound2 = 0.2f * S;

    int i = 4 * tid + blockIdx.y;
    if (tid < 196) {
        const uint4* row = (const uint4*)(g_packed + i * NN);
        float acc1 = 0.f, acc2 = 0.f, running = 0.f;
        for (int c4 = 0; c4 < NN / 4; c4++) {
            uint4 p = row[c4];
#define DTM_ELEM(pp) { unsigned _idx = (pp) & 0xFFFFu; float _fd2 = (float)((pp) >> 16); \
                       float _w = img[_idx]; float _cb = running; running = _cb + _w;   \
                       acc1 += fminf(fmaxf(bound1 - _cb, 0.f), _w) * _fd2;              \
                       acc2 += fminf(fmaxf(bound2 - _cb, 0.f), _w) * _fd2; }
            DTM_ELEM(p.x); DTM_ELEM(p.y); DTM_ELEM(p.z); DTM_ELEM(p.w);
#undef DTM_ELEM
            if (running >= bound2) break;   // all further eff are exactly 0
        }
        g_fvals[(0 * MAXB + m) * NN + i] = sqrtf(acc1 / bound1);
        g_fvals[(1 * MAXB + m) * NN + i] = sqrtf(acc2 / bound2);
    }
}

// ---------------------------------------------------------------------------
// Kernel C: hybrid register/smem bitonic sort + batched union-find with
// per-sub single-root fast path (match-based) + branchless slow path
// + fused landscape. Pairs stored at slot = loser root id.
// ---------------------------------------------------------------------------
struct SmemC {
    unsigned long long keys[1024];
    float vals[NN];
    unsigned order32[NN + 4];        // (yj<<24)|(xj<<16)|j per rank
    unsigned par32[NN + 2];          // root: (birth_pos<<16)|root ; else low16=parent
                                     // [NN], [NN+1] = write-only dummy slots
    unsigned short pos_[NN];
    unsigned char nbm[NN + 4];       // per-rank eligible-neighbor bitmask (+pad)
    float2 spBD[NN + 1];             // (birth, death) per loser-root slot; [NN]=dummy
};

// one bitonic compare-exchange stage in registers (jj<=16), lane-local via shfl
__device__ __forceinline__ void reg_stage(unsigned long long v[4], int w, int lane,
                                          int k, int jj) {
#pragma unroll
    for (int q = 0; q < 4; q++) {
        int i = (w << 7) + (q << 5) + lane;
        unsigned long long p = __shfl_xor_sync(0xFFFFFFFFu, v[q], jj);
        bool up = ((i & k) == 0);
        bool lowidx = ((lane & jj) == 0);
        bool keepmin = (up == lowidx);
        bool less = (v[q] < p);
        v[q] = (less == keepmin) ? v[q] : p;
    }
}

template <int DIR>
__device__ __forceinline__ void pairs_body(SmemC* s, int g, int m) {
    int tid = threadIdx.x;
    int lane = tid & 31, warp = tid >> 5;
    const unsigned EMASK = DIR ? 0xFFu : 0x0Fu;
    const unsigned INV = 0xFFFFFFFFu;
    const unsigned FULL = 0xFFFFFFFFu;

    for (int j = tid; j < NN; j += 256) {
        float v = g_fvals[(g * MAXB + m) * NN + j];
        s->vals[j] = v;
        float kf = DIR ? -v : v;  // dir1: superlevel via -x
        unsigned int u = __float_as_uint(kf);
        u = (u & 0x80000000u) ? ~u : (u | 0x80000000u);  // sortable transform
        s->keys[j] = ((unsigned long long)u << 32) | (unsigned int)j;  // stable ties by j
        s->spBD[j] = make_float2(0.f, 0.f);
    }
    for (int j = NN + tid; j < 1024; j += 256) s->keys[j] = ~0ULL;
    __syncthreads();

    // ---- hybrid bitonic sort of 1024 u64 keys ----
    // register layout: lane handles elements (w*128 + q*32 + lane), q=0..3
    {
        unsigned long long v[4];
#pragma unroll
        for (int q = 0; q < 4; q++) v[q] = s->keys[(warp << 7) + (q << 5) + lane];
        // k = 2..32 entirely in registers (15 stages, no barriers)
#pragma unroll
        for (int k = 2; k <= 32; k <<= 1)
            for (int jj = k >> 1; jj >= 1; jj >>= 1)
                reg_stage(v, warp, lane, k, jj);
#pragma unroll
        for (int q = 0; q < 4; q++) s->keys[(warp << 7) + (q << 5) + lane] = v[q];
        __syncthreads();

        for (int k = 64; k <= 1024; k <<= 1) {
            for (int jj = k >> 1; jj >= 32; jj >>= 1) {
                for (int i = tid; i < 1024; i += 256) {
                    int ixj = i ^ jj;
                    if (ixj > i) {
                        unsigned long long a = s->keys[i], b = s->keys[ixj];
                        bool up = ((i & k) == 0);
                        if ((a > b) == up) { s->keys[i] = b; s->keys[ixj] = a; }
                    }
                }
                __syncthreads();
            }
            // register tail: jj = 16..1
#pragma unroll
            for (int q = 0; q < 4; q++) v[q] = s->keys[(warp << 7) + (q << 5) + lane];
            for (int jj = 16; jj >= 1; jj >>= 1)
                reg_stage(v, warp, lane, k, jj);
#pragma unroll
            for (int q = 0; q < 4; q++) s->keys[(warp << 7) + (q << 5) + lane] = v[q];
            __syncthreads();
        }
    }

    for (int r = tid; r < NN; r += 256) {
        int j = (int)(unsigned int)s->keys[r];
        int xj = j / GRID, yj = j % GRID;
        s->order32[r] = (unsigned)j | ((unsigned)xj << 16) | ((unsigned)yj << 24);
        s->pos_[j] = (unsigned short)r;
        s->par32[j] = ((unsigned)r << 16) | (unsigned)j;   // root: birth<<16 | self
    }
    if (tid < 4) {
        s->order32[NN + tid] = 0u;
        s->nbm[NN + tid] = 0;
    }
    __syncthreads();

    // precompute per-rank eligible-neighbor bitmask (pos[u] < r, in bounds)
    for (int r = tid; r < NN; r += 256) {
        unsigned o = s->order32[r];
        int v = (int)(o & 0xFFFFu);
        int xv = (int)((o >> 16) & 0xFFu), yv = (int)(o >> 24);
        unsigned mask = 0u;
#pragma unroll
        for (int l = 0; l < 8; l++) {
            int xu = xv + c_dxs[l], yu = yv + c_dys[l];
            if ((unsigned)xu < (unsigned)GRID && (unsigned)yu < (unsigned)GRID &&
                (int)s->pos_[v + c_off[l]] < r)
                mask |= 1u << l;
        }
        s->nbm[r] = (unsigned char)mask;
    }
    __syncthreads();

    // ---- batched union-find: warp 0. 4 vertices/step, 8 lanes each.
    // packed = (birth_pos<<16)|root; min packed wins; fresh vertex always loses.
    if (tid < 32) {
        volatile unsigned* par = s->par32;
        int sub = lane >> 3, sl = lane & 7;
        unsigned lmlt = (1u << lane) - 1u;
        unsigned submask = 0xFFu << (sub << 3);
        unsigned em = (unsigned)s->nbm[sub] & EMASK;
        unsigned ov = s->order32[sub];
        for (int base = 0; base < NN; base += 4) {
            // prefetch next batch's mask/vertex (independent of par state)
            unsigned em_n = (unsigned)s->nbm[base + 4 + sub] & EMASK;
            unsigned ov_n = s->order32[base + 4 + sub];

            // optimistic finds against pre-batch parent state
            unsigned cur = INV;
            if ((em >> sl) & 1u) {
                int xx = (int)(ov & 0xFFFFu) + c_off[sl];
                for (;;) {  // find, 2 levels/iter with path halving
                    unsigned p32 = par[xx];
                    int pl = (int)(p32 & 0xFFFFu);
                    if (pl == xx) { cur = p32; break; }
                    unsigned q32 = par[pl];
                    int ql = (int)(q32 & 0xFFFFu);
                    if (ql == pl) { cur = q32; break; }
                    par[xx] = q32;      // halve: xx -> grandparent
                    xx = ql;
                }
            }

            bool valid = (cur != INV);
            // per-sub single-root fast check, full-warp intrinsics only:
            // lane ok iff all valid lanes of ITS sub share its root AND root
            // predates the batch. Then every sub's merge is {pre-batch root}
            // U {fresh vertex}: root wins, nothing dies, only (v,v) pairs.
            unsigned vmask = __ballot_sync(FULL, valid);
            unsigned grp = __match_any_sync(FULL, cur);
            bool okl = !valid || ((((grp | ~vmask) & submask) == submask) &&
                                  ((cur >> 16) < (unsigned)base));
            if (__all_sync(FULL, okl)) {
                // all merges are fresh-vertex joins: no pairs, just joins (branchless)
                unsigned fa = valid ? (ov & 0xFFFFu) : (unsigned)NN;
                par[fa] = cur;   // sub-uniform value; benign race within sub
            } else {
                // ---- exact serial 4-substep fix-up, branchless stores ----
                unsigned pvall = ((unsigned)(base + sub) << 16) | (ov & 0xFFFFu);
                unsigned pv0 = __shfl_sync(FULL, pvall, 0);
                unsigned pv1 = __shfl_sync(FULL, pvall, 8);
                unsigned pv2 = __shfl_sync(FULL, pvall, 16);
                unsigned pv3 = __shfl_sync(FULL, pvall, 24);
#pragma unroll
                for (int j = 0; j < 4; j++) {
                    unsigned pvj = (j < 2) ? (j == 0 ? pv0 : pv1) : (j == 2 ? pv2 : pv3);
                    unsigned grp2 = (j == 0) ? grp : __match_any_sync(FULL, cur);
                    bool valid2 = (cur != INV);
                    bool inj = (sub == j);
                    unsigned wjj = __reduce_min_sync(FULL, (valid2 && inj) ? cur : INV);
                    bool anyv = (wjj != INV);
                    bool deadval = inj && valid2 && (cur != wjj);
                    unsigned dmask = __ballot_sync(FULL, deadval);
                    bool leader = deadval && ((grp2 & dmask & lmlt) == 0u);
                    // branchless stores via dummy slots (no BSSY/BSYNC)
                    unsigned slot = leader ? (cur & 0xFFFFu) : (unsigned)NN;
                    unsigned bp = deadval ? (cur >> 16) : 0u;
                    int lbv = (int)(s->order32[bp] & 0xFFFFu);
                    unsigned vj = pvj & 0xFFFFu;
                    float Bv, Dv;
                    if (DIR == 0) { Bv = s->vals[lbv]; Dv = s->vals[vj]; }
                    else          { Bv = s->vals[vj];  Dv = s->vals[lbv]; }
                    s->spBD[slot] = make_float2(Bv, Dv);
                    par[slot] = wjj;                       // loser root -> winner
                    unsigned fa = (anyv && lane == 0) ? vj : (unsigned)(NN + 1);
                    par[fa] = wjj;                         // fresh vertex joins winner
                    // stale fix (registers only)
                    if (sub > j && valid2) {
                        bool stale = ((grp2 & dmask) != 0u) || (anyv && cur == pvj);
                        if (stale) cur = wjj;
                    }
                }
            }
            __syncwarp();
            em = em_n;
            ov = ov_n;
        }
    }
    __syncthreads();

    // ---- fused landscape top-K: 32 t-values, warp per t ----
    int K = g ? 3 : 2;
    float start = g ? 1.0f : 0.0f;
    int fbase = m * 320 + (g ? 128 : 0);
    for (int ti = warp; ti < 32; ti += 8) {
        float t = start + 7.0f * (float)ti / 31.0f;
        float a0 = -1.f, a1 = -1.f, a2 = -1.f;
        for (int j = lane; j < NN; j += 32) {
            float2 bd = s->spBD[j];
            float tent = fmaxf(fminf(t - bd.x, bd.y - t), 0.f);
            if (tent > a2) {
                if (tent > a0)      { a2 = a1; a1 = a0; a0 = tent; }
                else if (tent > a1) { a2 = a1; a1 = tent; }
                else                { a2 = tent; }
            }
        }
        for (int kk = 0; kk < K; kk++) {
            float w = a0;
#pragma unroll
            for (int off = 16; off; off >>= 1) w = fmaxf(w, __shfl_xor_sync(0xFFFFFFFFu, w, off));
            unsigned bal = __ballot_sync(0xFFFFFFFFu, a0 == w);
            int src = __ffs(bal) - 1;
            if (lane == src) { a0 = a1; a1 = a2; a2 = -1.f; }
            if (lane == 0) g_feats[fbase + (DIR * K + kk) * 32 + ti] = w;
        }
    }
}

__global__ void pairs_kernel() {
    __shared__ SmemC smc;
    int task = blockIdx.x;
    int dir = task & 1;
    int g = (task >> 1) & 1;
    int m = task >> 2;
    if (dir == 0) pairs_body<0>(&smc, g, m);
    else          pairs_body<1>(&smc, g, m);
}

// ---------------------------------------------------------------------------
// Kernel D: tiny MLP. Block per image, 512 threads, warp-per-unit dots.
// ---------------------------------------------------------------------------
__global__ void mlp_kernel(const float* __restrict__ wg1, const float* __restrict__ bg1,
                           const float* __restrict__ wg2, const float* __restrict__ bg2,
                           const float* __restrict__ wfc, const float* __restrict__ bfc,
                           float* __restrict__ out) {
    int m = blockIdx.x;
    __shared__ float sx[64];
    int tid = threadIdx.x;
    int lane = tid & 31, w = tid >> 5;   // 16 warps
    const float* feats = g_feats + m * 320;

#pragma unroll
    for (int i = 0; i < 2; i++) {
        int u = w * 2 + i;
        float a = 0.f;
#pragma unroll
        for (int c = lane; c < 128; c += 32) a += feats[c] * wg1[u * 128 + c];
#pragma unroll
        for (int off = 16; off; off >>= 1) a += __shfl_xor_sync(0xFFFFFFFFu, a, off);
        if (lane == 0) sx[u] = fmaxf(a + bg1[u], 0.f);
    }
#pragma unroll
    for (int i = 0; i < 2; i++) {
        int u = w * 2 + i;
        float a = 0.f;
#pragma unroll
        for (int c = lane; c < 192; c += 32) a += feats[128 + c] * wg2[u * 192 + c];
#pragma unroll
        for (int off = 16; off; off >>= 1) a += __shfl_xor_sync(0xFFFFFFFFu, a, off);
        if (lane == 0) sx[32 + u] = fmaxf(a + bg2[u], 0.f);
    }
    __syncthreads();
    if (tid < 10) {
        float a = bfc[tid];
#pragma unroll
        for (int c = 0; c < 64; c++) a += sx[c] * wfc[tid * 64 + c];
        out[m * 10 + tid] = a;
    }
}

// ---------------------------------------------------------------------------
extern "C" void kernel_launch(void* const* d_in, const int* in_sizes, int n_in,
                              void* d_out, int out_size) {
    const float* x   = (const float*)d_in[0];
    const float* wg1 = (const float*)d_in[1];
    const float* bg1 = (const float*)d_in[2];
    const float* wg2 = (const float*)d_in[3];
    const float* bg2 = (const float*)d_in[4];
    const float* wfc = (const float*)d_in[5];
    const float* bfc = (const float*)d_in[6];
    float* out = (float*)d_out;
    int B = in_sizes[0] / NN;
    if (B > MAXB) B = MAXB;

    build_sort_table_kernel<<<NN, 256>>>();
    dtm_kernel<<<dim3(B, 4), 256>>>(x);
    pairs_kernel<<<B * 4, 256>>>();
    mlp_kernel<<<B, 512>>>(wg1, bg1, wg2, bg2, wfc, bfc, out);
}

// round 15
// speedup vs baseline: 1.5455x; 1.0003x over previous
#include <cuda_runtime.h>

#define NN 784
#define GRID 28
#define MAXB 64
#define MAXD2 1459   // d2 in [0, 27^2+27^2=1458]

// Scratch (device globals — no allocations allowed)
__device__ unsigned g_packed[NN * NN];           // [i][rank] -> (d2<<16)|idx
__device__ float g_fvals[2 * MAXB * NN];         // [g][m][i] dtm values
__device__ float g_feats[MAXB * 320];            // landscape features per image

__constant__ int c_dxs[8] = {-1, 1, 0, 0, -1, -1, 1, 1};
__constant__ int c_dys[8] = {0, 0, -1, 1, -1, 1, -1, 1};
__constant__ int c_off[8] = {-28, 28, -1, 1, -29, -27, 27, 29};

// ---------------------------------------------------------------------------
// Kernel A: stable argsort of squared grid distances per point (counting sort)
// writes packed (d2<<16)|idx
// ---------------------------------------------------------------------------
__global__ void build_sort_table_kernel() {
    int i = blockIdx.x;
    int xi = i / GRID, yi = i % GRID;
    __shared__ unsigned int hist[MAXD2];
    __shared__ unsigned short d2a[NN];
    __shared__ unsigned int wsum[8];
    int tid = threadIdx.x;
    int lane = tid & 31, warp = tid >> 5;

    for (int t = tid; t < MAXD2; t += 256) hist[t] = 0u;
    __syncthreads();
    for (int j = tid; j < NN; j += 256) {
        int dx = j / GRID - xi, dy = j % GRID - yi;
        int d2 = dx * dx + dy * dy;
        d2a[j] = (unsigned short)d2;
        atomicAdd(&hist[d2], 1u);
    }
    __syncthreads();

    // exclusive scan of hist[0..1458] (6 entries per thread, 256 threads)
    unsigned int lv[6];
    unsigned int s = 0u;
    int base = tid * 6;
#pragma unroll
    for (int c = 0; c < 6; c++) {
        unsigned int v = (base + c < MAXD2) ? hist[base + c] : 0u;
        lv[c] = s;
        s += v;
    }
    unsigned int inc = s;
#pragma unroll
    for (int off = 1; off < 32; off <<= 1) {
        unsigned int t = __shfl_up_sync(0xFFFFFFFFu, inc, off);
        if (lane >= off) inc += t;
    }
    if (lane == 31) wsum[warp] = inc;
    __syncthreads();
    if (tid == 0) {
        unsigned int a = 0u;
        for (int w = 0; w < 8; w++) { unsigned int t = wsum[w]; wsum[w] = a; a += t; }
    }
    __syncthreads();
    unsigned int off0 = wsum[warp] + (inc - s);
    __syncthreads();  // all reads of hist done before overwrite
#pragma unroll
    for (int c = 0; c < 6; c++)
        if (base + c < MAXD2) hist[base + c] = off0 + lv[c];
    __syncthreads();

    // Stable scatter: warps serialized in ascending-j order
    for (int gq = 0; gq < 25; gq++) {
        if (warp == (gq & 7)) {
            int j = gq * 32 + lane;
            bool valid = (j < NN);
            unsigned int key = valid ? (unsigned int)d2a[j] : 0xFFFFu;
            unsigned int mk = __match_any_sync(0xFFFFFFFFu, key);
            int leader = __ffs(mk) - 1;
            int pre = __popc(mk & ((1u << lane) - 1u));
            unsigned int b0 = 0u;
            if (lane == leader && valid) b0 = atomicAdd(&hist[key], (unsigned int)__popc(mk));
            b0 = __shfl_sync(0xFFFFFFFFu, b0, leader);
            if (valid) g_packed[i * NN + b0 + pre] = (key << 16) | (unsigned)j;
        }
        __syncthreads();
    }
}

// ---------------------------------------------------------------------------
// Kernel B: DTM, thread-per-point sequential scan, both m0 in one pass.
// Grid (B, 4): block y handles points {4*tid + y | tid < 196}.
// ---------------------------------------------------------------------------
__global__ void dtm_kernel(const float* __restrict__ x) {
    int m = blockIdx.x;
    __shared__ float img[NN];
    __shared__ float red[8];
    int tid = threadIdx.x;
    int lane = tid & 31, warp = tid >> 5;

    float ps = 0.f;
    for (int j = tid; j < NN; j += 256) {
        float v = x[m * NN + j];
        img[j] = v;
        ps += v;
    }
#pragma unroll
    for (int off = 16; off; off >>= 1) ps += __shfl_xor_sync(0xFFFFFFFFu, ps, off);
    if (lane == 0) red[warp] = ps;
    __syncthreads();
    float S = 0.f;
#pragma unroll
    for (int w = 0; w < 8; w++) S += red[w];
    float bound1 = 0.05f * S;
    float bound2 = 0.2f * S;

    int i = 4 * tid + blockIdx.y;
    if (tid < 196) {
        const uint4* row = (const uint4*)(g_packed + i * NN);
        float acc1 = 0.f, acc2 = 0.f, running = 0.f;
        for (int c4 = 0; c4 < NN / 4; c4++) {
            uint4 p = row[c4];
#define DTM_ELEM(pp) { unsigned _idx = (pp) & 0xFFFFu; float _fd2 = (float)((pp) >> 16); \
                       float _w = img[_idx]; float _cb = running; running = _cb + _w;   \
                       acc1 += fminf(fmaxf(bound1 - _cb, 0.f), _w) * _fd2;              \
                       acc2 += fminf(fmaxf(bound2 - _cb, 0.f), _w) * _fd2; }
            DTM_ELEM(p.x); DTM_ELEM(p.y); DTM_ELEM(p.z); DTM_ELEM(p.w);
#undef DTM_ELEM
            if (running >= bound2) break;   // all further eff are exactly 0
        }
        g_fvals[(0 * MAXB + m) * NN + i] = sqrtf(acc1 / bound1);
        g_fvals[(1 * MAXB + m) * NN + i] = sqrtf(acc2 / bound2);
    }
}

// ---------------------------------------------------------------------------
// Kernel C: hybrid register/smem bitonic sort + batched union-find with
// per-sub single-root fast path + bad-subs-only slow path + fused landscape.
// Pairs stored at slot = loser root id (unique per run; zero-fill -> tent 0).
// ---------------------------------------------------------------------------
struct SmemC {
    unsigned long long keys[1024];
    float vals[NN];
    unsigned order32[NN + 4];        // (yj<<24)|(xj<<16)|j per rank
    unsigned par32[NN + 2];          // root: (birth_pos<<16)|root ; else low16=parent
                                     // [NN], [NN+1] = write-only dummy slots
    unsigned short pos_[NN];
    unsigned char nbm[NN + 4];       // per-rank eligible-neighbor bitmask (+pad)
    float2 spBD[NN + 1];             // (birth, death) per loser-root slot; [NN]=dummy
};

// one bitonic compare-exchange stage in registers (jj<=16), lane-local via shfl
__device__ __forceinline__ void reg_stage(unsigned long long v[4], int w, int lane,
                                          int k, int jj) {
#pragma unroll
    for (int q = 0; q < 4; q++) {
        int i = (w << 7) + (q << 5) + lane;
        unsigned long long p = __shfl_xor_sync(0xFFFFFFFFu, v[q], jj);
        bool up = ((i & k) == 0);
        bool lowidx = ((lane & jj) == 0);
        bool keepmin = (up == lowidx);
        bool less = (v[q] < p);
        v[q] = (less == keepmin) ? v[q] : p;
    }
}

template <int DIR>
__device__ __forceinline__ void pairs_body(SmemC* s, int g, int m) {
    int tid = threadIdx.x;
    int lane = tid & 31, warp = tid >> 5;
    const unsigned EMASK = DIR ? 0xFFu : 0x0Fu;
    const unsigned INV = 0xFFFFFFFFu;
    const unsigned FULL = 0xFFFFFFFFu;

    for (int j = tid; j < NN; j += 256) {
        float v = g_fvals[(g * MAXB + m) * NN + j];
        s->vals[j] = v;
        float kf = DIR ? -v : v;  // dir1: superlevel via -x
        unsigned int u = __float_as_uint(kf);
        u = (u & 0x80000000u) ? ~u : (u | 0x80000000u);  // sortable transform
        s->keys[j] = ((unsigned long long)u << 32) | (unsigned int)j;  // stable ties by j
        s->spBD[j] = make_float2(0.f, 0.f);
    }
    for (int j = NN + tid; j < 1024; j += 256) s->keys[j] = ~0ULL;
    __syncthreads();

    // ---- hybrid bitonic sort of 1024 u64 keys ----
    // register layout: lane handles elements (w*128 + q*32 + lane), q=0..3
    {
        unsigned long long v[4];
#pragma unroll
        for (int q = 0; q < 4; q++) v[q] = s->keys[(warp << 7) + (q << 5) + lane];
        // k = 2..32 entirely in registers (15 stages, no barriers)
#pragma unroll
        for (int k = 2; k <= 32; k <<= 1)
            for (int jj = k >> 1; jj >= 1; jj >>= 1)
                reg_stage(v, warp, lane, k, jj);
#pragma unroll
        for (int q = 0; q < 4; q++) s->keys[(warp << 7) + (q << 5) + lane] = v[q];
        __syncthreads();

        for (int k = 64; k <= 1024; k <<= 1) {
            for (int jj = k >> 1; jj >= 32; jj >>= 1) {
                for (int i = tid; i < 1024; i += 256) {
                    int ixj = i ^ jj;
                    if (ixj > i) {
                        unsigned long long a = s->keys[i], b = s->keys[ixj];
                        bool up = ((i & k) == 0);
                        if ((a > b) == up) { s->keys[i] = b; s->keys[ixj] = a; }
                    }
                }
                __syncthreads();
            }
            // register tail: jj = 16..1
#pragma unroll
            for (int q = 0; q < 4; q++) v[q] = s->keys[(warp << 7) + (q << 5) + lane];
            for (int jj = 16; jj >= 1; jj >>= 1)
                reg_stage(v, warp, lane, k, jj);
#pragma unroll
            for (int q = 0; q < 4; q++) s->keys[(warp << 7) + (q << 5) + lane] = v[q];
            __syncthreads();
        }
    }

    for (int r = tid; r < NN; r += 256) {
        int j = (int)(unsigned int)s->keys[r];
        int xj = j / GRID, yj = j % GRID;
        s->order32[r] = (unsigned)j | ((unsigned)xj << 16) | ((unsigned)yj << 24);
        s->pos_[j] = (unsigned short)r;
        s->par32[j] = ((unsigned)r << 16) | (unsigned)j;   // root: birth<<16 | self
    }
    if (tid < 4) {
        s->order32[NN + tid] = 0u;
        s->nbm[NN + tid] = 0;
    }
    __syncthreads();

    // precompute per-rank eligible-neighbor bitmask (pos[u] < r, in bounds)
    for (int r = tid; r < NN; r += 256) {
        unsigned o = s->order32[r];
        int v = (int)(o & 0xFFFFu);
        int xv = (int)((o >> 16) & 0xFFu), yv = (int)(o >> 24);
        unsigned mask = 0u;
#pragma unroll
        for (int l = 0; l < 8; l++) {
            int xu = xv + c_dxs[l], yu = yv + c_dys[l];
            if ((unsigned)xu < (unsigned)GRID && (unsigned)yu < (unsigned)GRID &&
                (int)s->pos_[v + c_off[l]] < r)
                mask |= 1u << l;
        }
        s->nbm[r] = (unsigned char)mask;
    }
    __syncthreads();

    // ---- batched union-find: warp 0. 4 vertices/step, 8 lanes each.
    // packed = (birth_pos<<16)|root; min packed wins; fresh vertex always loses.
    if (tid < 32) {
        volatile unsigned* par = s->par32;
        int sub = lane >> 3, sl = lane & 7;
        unsigned lmlt = (1u << lane) - 1u;
        unsigned submask = 0xFFu << (sub << 3);
        unsigned em = (unsigned)s->nbm[sub] & EMASK;
        unsigned ov = s->order32[sub];
        for (int base = 0; base < NN; base += 4) {
            // prefetch next batch's mask/vertex (independent of par state)
            unsigned em_n = (unsigned)s->nbm[base + 4 + sub] & EMASK;
            unsigned ov_n = s->order32[base + 4 + sub];

            // optimistic finds against pre-batch parent state
            unsigned cur = INV;
            if ((em >> sl) & 1u) {
                int xx = (int)(ov & 0xFFFFu) + c_off[sl];
                for (;;) {  // find, 2 levels/iter with path halving
                    unsigned p32 = par[xx];
                    int pl = (int)(p32 & 0xFFFFu);
                    if (pl == xx) { cur = p32; break; }
                    unsigned q32 = par[pl];
                    int ql = (int)(q32 & 0xFFFFu);
                    if (ql == pl) { cur = q32; break; }
                    par[xx] = q32;      // halve: xx -> grandparent
                    xx = ql;
                }
            }

            bool valid = (cur != INV);
            // per-sub single-root check, full-warp intrinsics only:
            // lane ok iff all valid lanes of ITS sub share its root AND root
            // predates the batch. Ok sub's merge = {pre-batch root} U {fresh}:
            // root wins, nothing dies, only (v,v) pairs -> just a join.
            unsigned vmask = __ballot_sync(FULL, valid);
            unsigned grp = __match_any_sync(FULL, cur);
            bool okl = !valid || ((((grp | ~vmask) & submask) == submask) &&
                                  ((cur >> 16) < (unsigned)base));
            unsigned badl = __ballot_sync(FULL, !okl);
            if (badl == 0u) {
                unsigned fa = valid ? (ov & 0xFFFFu) : (unsigned)NN;
                par[fa] = cur;   // sub-uniform value; benign race within sub
            } else {
                // ---- bad-subs-only fix-up ----
                // 1) ok subs join immediately (exact: joins never kill roots;
                //    eligibility guarantees rank ordering is respected)
                unsigned fa = (okl && valid) ? (ov & 0xFFFFu) : (unsigned)NN;
                par[fa] = cur;
                __syncwarp();
                // 2) bad lanes with an in-batch-born root: one re-read redirects
                //    to the pre-batch root if that vertex joined (join stores the
                //    full packed root); unchanged otherwise (self entry).
                if (!okl && valid && (cur >> 16) >= (unsigned)base)
                    cur = par[cur & 0xFFFFu];
                unsigned pvall = ((unsigned)(base + sub) << 16) | (ov & 0xFFFFu);
                unsigned pv0 = __shfl_sync(FULL, pvall, 0);
                unsigned pv1 = __shfl_sync(FULL, pvall, 8);
                unsigned pv2 = __shfl_sync(FULL, pvall, 16);
                unsigned pv3 = __shfl_sync(FULL, pvall, 24);
                // 3) warp-uniform loop over bad subs only (ascending)
                unsigned bsub = 0u;
#pragma unroll
                for (int j = 0; j < 4; j++)
                    if ((badl >> (j << 3)) & 0xFFu) bsub |= 1u << j;
                while (bsub) {
                    int j = __ffs(bsub) - 1;
                    bsub &= bsub - 1;
                    unsigned pvj = (j < 2) ? (j == 0 ? pv0 : pv1) : (j == 2 ? pv2 : pv3);
                    unsigned grp2 = __match_any_sync(FULL, cur);
                    bool valid2 = (cur != INV);
                    bool inj = (sub == j);
                    unsigned wjj = __reduce_min_sync(FULL, (valid2 && inj) ? cur : INV);
                    bool anyv = (wjj != INV);
                    bool deadval = inj && valid2 && (cur != wjj);
                    unsigned dmask = __ballot_sync(FULL, deadval);
                    bool leader = deadval && ((grp2 & dmask & lmlt) == 0u);
                    // branchless stores via dummy slots (no BSSY/BSYNC)
                    unsigned slot = leader ? (cur & 0xFFFFu) : (unsigned)NN;
                    unsigned bp = deadval ? (cur >> 16) : 0u;
                    int lbv = (int)(s->order32[bp] & 0xFFFFu);
                    unsigned vj = pvj & 0xFFFFu;
                    float Bv, Dv;
                    if (DIR == 0) { Bv = s->vals[lbv]; Dv = s->vals[vj]; }
                    else          { Bv = s->vals[vj];  Dv = s->vals[lbv]; }
                    s->spBD[slot] = make_float2(Bv, Dv);
                    par[slot] = wjj;                       // loser root -> winner
                    unsigned fa2 = (anyv && lane == 0) ? vj : (unsigned)(NN + 1);
                    par[fa2] = wjj;                        // fresh vertex joins winner
                    // stale fix (registers only)
                    if (sub > j && valid2) {
                        bool stale = ((grp2 & dmask) != 0u) || (anyv && cur == pvj);
                        if (stale) cur = wjj;
                    }
                }
            }
            __syncwarp();
            em = em_n;
            ov = ov_n;
        }
    }
    __syncthreads();

    // ---- fused landscape top-K: 32 t-values, warp per t ----
    int K = g ? 3 : 2;
    float start = g ? 1.0f : 0.0f;
    int fbase = m * 320 + (g ? 128 : 0);
    for (int ti = warp; ti < 32; ti += 8) {
        float t = start + 7.0f * (float)ti / 31.0f;
        float a0 = -1.f, a1 = -1.f, a2 = -1.f;
        for (int j = lane; j < NN; j += 32) {
            float2 bd = s->spBD[j];
            float tent = fmaxf(fminf(t - bd.x, bd.y - t), 0.f);
            if (tent > a2) {
                if (tent > a0)      { a2 = a1; a1 = a0; a0 = tent; }
                else if (tent > a1) { a2 = a1; a1 = tent; }
                else                { a2 = tent; }
            }
        }
        for (int kk = 0; kk < K; kk++) {
            float w = a0;
#pragma unroll
            for (int off = 16; off; off >>= 1) w = fmaxf(w, __shfl_xor_sync(0xFFFFFFFFu, w, off));
            unsigned bal = __ballot_sync(0xFFFFFFFFu, a0 == w);
            int src = __ffs(bal) - 1;
            if (lane == src) { a0 = a1; a1 = a2; a2 = -1.f; }
            if (lane == 0) g_feats[fbase + (DIR * K + kk) * 32 + ti] = w;
        }
    }
}

__global__ void pairs_kernel() {
    __shared__ SmemC smc;
    int task = blockIdx.x;
    int dir = task & 1;
    int g = (task >> 1) & 1;
    int m = task >> 2;
    if (dir == 0) pairs_body<0>(&smc, g, m);
    else          pairs_body<1>(&smc, g, m);
}

// ---------------------------------------------------------------------------
// Kernel D: tiny MLP. Block per image, 512 threads, warp-per-unit dots.
// ---------------------------------------------------------------------------
__global__ void mlp_kernel(const float* __restrict__ wg1, const float* __restrict__ bg1,
                           const float* __restrict__ wg2, const float* __restrict__ bg2,
                           const float* __restrict__ wfc, const float* __restrict__ bfc,
                           float* __restrict__ out) {
    int m = blockIdx.x;
    __shared__ float sx[64];
    int tid = threadIdx.x;
    int lane = tid & 31, w = tid >> 5;   // 16 warps
    const float* feats = g_feats + m * 320;

#pragma unroll
    for (int i = 0; i < 2; i++) {
        int u = w * 2 + i;
        float a = 0.f;
#pragma unroll
        for (int c = lane; c < 128; c += 32) a += feats[c] * wg1[u * 128 + c];
#pragma unroll
        for (int off = 16; off; off >>= 1) a += __shfl_xor_sync(0xFFFFFFFFu, a, off);
        if (lane == 0) sx[u] = fmaxf(a + bg1[u], 0.f);
    }
#pragma unroll
    for (int i = 0; i < 2; i++) {
        int u = w * 2 + i;
        float a = 0.f;
#pragma unroll
        for (int c = lane; c < 192; c += 32) a += feats[128 + c] * wg2[u * 192 + c];
#pragma unroll
        for (int off = 16; off; off >>= 1) a += __shfl_xor_sync(0xFFFFFFFFu, a, off);
        if (lane == 0) sx[32 + u] = fmaxf(a + bg2[u], 0.f);
    }
    __syncthreads();
    if (tid < 10) {
        float a = bfc[tid];
#pragma unroll
        for (int c = 0; c < 64; c++) a += sx[c] * wfc[tid * 64 + c];
        out[m * 10 + tid] = a;
    }
}

// ---------------------------------------------------------------------------
extern "C" void kernel_launch(void* const* d_in, const int* in_sizes, int n_in,
                              void* d_out, int out_size) {
    const float* x   = (const float*)d_in[0];
    const float* wg1 = (const float*)d_in[1];
    const float* bg1 = (const float*)d_in[2];
    const float* wg2 = (const float*)d_in[3];
    const float* bg2 = (const float*)d_in[4];
    const float* wfc = (const float*)d_in[5];
    const float* bfc = (const float*)d_in[6];
    float* out = (float*)d_out;
    int B = in_sizes[0] / NN;
    if (B > MAXB) B = MAXB;

    build_sort_table_kernel<<<NN, 256>>>();
    dtm_kernel<<<dim3(B, 4), 256>>>(x);
    pairs_kernel<<<B * 4, 256>>>();
    mlp_kernel<<<B, 512>>>(wg1, bg1, wg2, bg2, wfc, bfc, out);
}

// round 16
// speedup vs baseline: 1.6008x; 1.0358x over previous
#include <cuda_runtime.h>

#define NN 784
#define GRID 28
#define MAXB 64
#define MAXD2 1459   // d2 in [0, 27^2+27^2=1458]

// Scratch (device globals — no allocations allowed)
__device__ unsigned g_packed[NN * NN];           // [i][rank] -> (d2<<16)|idx
__device__ float g_fvals[2 * MAXB * NN];         // [g][m][i] dtm values
__device__ float g_feats[MAXB * 320];            // landscape features per image

__constant__ int c_dxs[8] = {-1, 1, 0, 0, -1, -1, 1, 1};
__constant__ int c_dys[8] = {0, 0, -1, 1, -1, 1, -1, 1};
__constant__ int c_off[8] = {-28, 28, -1, 1, -29, -27, 27, 29};

// ---------------------------------------------------------------------------
// Kernel A: stable argsort of squared grid distances per point (counting sort)
// writes packed (d2<<16)|idx
// ---------------------------------------------------------------------------
__global__ void build_sort_table_kernel() {
    int i = blockIdx.x;
    int xi = i / GRID, yi = i % GRID;
    __shared__ unsigned int hist[MAXD2];
    __shared__ unsigned short d2a[NN];
    __shared__ unsigned int wsum[8];
    int tid = threadIdx.x;
    int lane = tid & 31, warp = tid >> 5;

    for (int t = tid; t < MAXD2; t += 256) hist[t] = 0u;
    __syncthreads();
    for (int j = tid; j < NN; j += 256) {
        int dx = j / GRID - xi, dy = j % GRID - yi;
        int d2 = dx * dx + dy * dy;
        d2a[j] = (unsigned short)d2;
        atomicAdd(&hist[d2], 1u);
    }
    __syncthreads();

    // exclusive scan of hist[0..1458] (6 entries per thread, 256 threads)
    unsigned int lv[6];
    unsigned int s = 0u;
    int base = tid * 6;
#pragma unroll
    for (int c = 0; c < 6; c++) {
        unsigned int v = (base + c < MAXD2) ? hist[base + c] : 0u;
        lv[c] = s;
        s += v;
    }
    unsigned int inc = s;
#pragma unroll
    for (int off = 1; off < 32; off <<= 1) {
        unsigned int t = __shfl_up_sync(0xFFFFFFFFu, inc, off);
        if (lane >= off) inc += t;
    }
    if (lane == 31) wsum[warp] = inc;
    __syncthreads();
    if (tid == 0) {
        unsigned int a = 0u;
        for (int w = 0; w < 8; w++) { unsigned int t = wsum[w]; wsum[w] = a; a += t; }
    }
    __syncthreads();
    unsigned int off0 = wsum[warp] + (inc - s);
    __syncthreads();  // all reads of hist done before overwrite
#pragma unroll
    for (int c = 0; c < 6; c++)
        if (base + c < MAXD2) hist[base + c] = off0 + lv[c];
    __syncthreads();

    // Stable scatter: warps serialized in ascending-j order
    for (int gq = 0; gq < 25; gq++) {
        if (warp == (gq & 7)) {
            int j = gq * 32 + lane;
            bool valid = (j < NN);
            unsigned int key = valid ? (unsigned int)d2a[j] : 0xFFFFu;
            unsigned int mk = __match_any_sync(0xFFFFFFFFu, key);
            int leader = __ffs(mk) - 1;
            int pre = __popc(mk & ((1u << lane) - 1u));
            unsigned int b0 = 0u;
            if (lane == leader && valid) b0 = atomicAdd(&hist[key], (unsigned int)__popc(mk));
            b0 = __shfl_sync(0xFFFFFFFFu, b0, leader);
            if (valid) g_packed[i * NN + b0 + pre] = (key << 16) | (unsigned)j;
        }
        __syncthreads();
    }
}

// ---------------------------------------------------------------------------
// Kernel B: DTM, thread-per-point sequential scan, both m0 in one pass.
// Grid (B, 4): block y handles points {4*tid + y | tid < 196}.
// ---------------------------------------------------------------------------
__global__ void dtm_kernel(const float* __restrict__ x) {
    int m = blockIdx.x;
    __shared__ float img[NN];
    __shared__ float red[8];
    int tid = threadIdx.x;
    int lane = tid & 31, warp = tid >> 5;

    float ps = 0.f;
    for (int j = tid; j < NN; j += 256) {
        float v = x[m * NN + j];
        img[j] = v;
        ps += v;
    }
#pragma unroll
    for (int off = 16; off; off >>= 1) ps += __shfl_xor_sync(0xFFFFFFFFu, ps, off);
    if (lane == 0) red[warp] = ps;
    __syncthreads();
    float S = 0.f;
#pragma unroll
    for (int w = 0; w < 8; w++) S += red[w];
    float bound1 = 0.05f * S;
    float bound2 = 0.2f * S;

    int i = 4 * tid + blockIdx.y;
    if (tid < 196) {
        const uint4* row = (const uint4*)(g_packed + i * NN);
        float acc1 = 0.f, acc2 = 0.f, running = 0.f;
        for (int c4 = 0; c4 < NN / 4; c4++) {
            uint4 p = row[c4];
#define DTM_ELEM(pp) { unsigned _idx = (pp) & 0xFFFFu; float _fd2 = (float)((pp) >> 16); \
                       float _w = img[_idx]; float _cb = running; running = _cb + _w;   \
                       acc1 += fminf(fmaxf(bound1 - _cb, 0.f), _w) * _fd2;              \
                       acc2 += fminf(fmaxf(bound2 - _cb, 0.f), _w) * _fd2; }
            DTM_ELEM(p.x); DTM_ELEM(p.y); DTM_ELEM(p.z); DTM_ELEM(p.w);
#undef DTM_ELEM
            if (running >= bound2) break;   // all further eff are exactly 0
        }
        g_fvals[(0 * MAXB + m) * NN + i] = sqrtf(acc1 / bound1);
        g_fvals[(1 * MAXB + m) * NN + i] = sqrtf(acc2 / bound2);
    }
}

// ---------------------------------------------------------------------------
// Kernel C: hybrid register/smem bitonic sort + batched union-find with
// branch-free fixed-point find, per-sub single-root fast path, bad-subs-only
// slow path + fused landscape. Pairs stored at slot = loser root id.
// ---------------------------------------------------------------------------
struct SmemC {
    unsigned long long keys[1024];
    float vals[NN];
    unsigned order32[NN + 4];        // (yj<<24)|(xj<<16)|j per rank
    unsigned par32[NN + 2];          // root: (birth_pos<<16)|root ; else low16=parent
                                     // [NN], [NN+1] = write-only dummy slots
    unsigned short pos_[NN];
    unsigned char nbm[NN + 4];       // per-rank eligible-neighbor bitmask (+pad)
    float2 spBD[NN + 1];             // (birth, death) per loser-root slot; [NN]=dummy
};

// one bitonic compare-exchange stage in registers (jj<=16), lane-local via shfl
__device__ __forceinline__ void reg_stage(unsigned long long v[4], int w, int lane,
                                          int k, int jj) {
#pragma unroll
    for (int q = 0; q < 4; q++) {
        int i = (w << 7) + (q << 5) + lane;
        unsigned long long p = __shfl_xor_sync(0xFFFFFFFFu, v[q], jj);
        bool up = ((i & k) == 0);
        bool lowidx = ((lane & jj) == 0);
        bool keepmin = (up == lowidx);
        bool less = (v[q] < p);
        v[q] = (less == keepmin) ? v[q] : p;
    }
}

template <int DIR>
__device__ __forceinline__ void pairs_body(SmemC* s, int g, int m) {
    int tid = threadIdx.x;
    int lane = tid & 31, warp = tid >> 5;
    const unsigned EMASK = DIR ? 0xFFu : 0x0Fu;
    const unsigned INV = 0xFFFFFFFFu;
    const unsigned FULL = 0xFFFFFFFFu;

    for (int j = tid; j < NN; j += 256) {
        float v = g_fvals[(g * MAXB + m) * NN + j];
        s->vals[j] = v;
        float kf = DIR ? -v : v;  // dir1: superlevel via -x
        unsigned int u = __float_as_uint(kf);
        u = (u & 0x80000000u) ? ~u : (u | 0x80000000u);  // sortable transform
        s->keys[j] = ((unsigned long long)u << 32) | (unsigned int)j;  // stable ties by j
        s->spBD[j] = make_float2(0.f, 0.f);
    }
    for (int j = NN + tid; j < 1024; j += 256) s->keys[j] = ~0ULL;
    __syncthreads();

    // ---- hybrid bitonic sort of 1024 u64 keys ----
    // register layout: lane handles elements (w*128 + q*32 + lane), q=0..3
    {
        unsigned long long v[4];
#pragma unroll
        for (int q = 0; q < 4; q++) v[q] = s->keys[(warp << 7) + (q << 5) + lane];
        // k = 2..32 entirely in registers (15 stages, no barriers)
#pragma unroll
        for (int k = 2; k <= 32; k <<= 1)
            for (int jj = k >> 1; jj >= 1; jj >>= 1)
                reg_stage(v, warp, lane, k, jj);
#pragma unroll
        for (int q = 0; q < 4; q++) s->keys[(warp << 7) + (q << 5) + lane] = v[q];
        __syncthreads();

        for (int k = 64; k <= 1024; k <<= 1) {
            for (int jj = k >> 1; jj >= 32; jj >>= 1) {
                for (int i = tid; i < 1024; i += 256) {
                    int ixj = i ^ jj;
                    if (ixj > i) {
                        unsigned long long a = s->keys[i], b = s->keys[ixj];
                        bool up = ((i & k) == 0);
                        if ((a > b) == up) { s->keys[i] = b; s->keys[ixj] = a; }
                    }
                }
                __syncthreads();
            }
            // register tail: jj = 16..1
#pragma unroll
            for (int q = 0; q < 4; q++) v[q] = s->keys[(warp << 7) + (q << 5) + lane];
            for (int jj = 16; jj >= 1; jj >>= 1)
                reg_stage(v, warp, lane, k, jj);
#pragma unroll
            for (int q = 0; q < 4; q++) s->keys[(warp << 7) + (q << 5) + lane] = v[q];
            __syncthreads();
        }
    }

    for (int r = tid; r < NN; r += 256) {
        int j = (int)(unsigned int)s->keys[r];
        int xj = j / GRID, yj = j % GRID;
        s->order32[r] = (unsigned)j | ((unsigned)xj << 16) | ((unsigned)yj << 24);
        s->pos_[j] = (unsigned short)r;
        s->par32[j] = ((unsigned)r << 16) | (unsigned)j;   // root: birth<<16 | self
    }
    if (tid < 4) {
        s->order32[NN + tid] = 0u;
        s->nbm[NN + tid] = 0;
    }
    if (tid < 2) s->par32[NN + tid] = 0u;   // dummy slots start valid
    __syncthreads();

    // precompute per-rank eligible-neighbor bitmask (pos[u] < r, in bounds)
    for (int r = tid; r < NN; r += 256) {
        unsigned o = s->order32[r];
        int v = (int)(o & 0xFFFFu);
        int xv = (int)((o >> 16) & 0xFFu), yv = (int)(o >> 24);
        unsigned mask = 0u;
#pragma unroll
        for (int l = 0; l < 8; l++) {
            int xu = xv + c_dxs[l], yu = yv + c_dys[l];
            if ((unsigned)xu < (unsigned)GRID && (unsigned)yu < (unsigned)GRID &&
                (int)s->pos_[v + c_off[l]] < r)
                mask |= 1u << l;
        }
        s->nbm[r] = (unsigned char)mask;
    }
    __syncthreads();

    // ---- batched union-find: warp 0. 4 vertices/step, 8 lanes each.
    // packed = (birth_pos<<16)|root; min packed wins; fresh vertex always loses.
    if (tid < 32) {
        volatile unsigned* par = s->par32;
        int sub = lane >> 3, sl = lane & 7;
        unsigned lmlt = (1u << lane) - 1u;
        unsigned submask = 0xFFu << (sub << 3);
        unsigned em = (unsigned)s->nbm[sub] & EMASK;
        unsigned ov = s->order32[sub];
        for (int base = 0; base < NN; base += 4) {
            // prefetch next batch's mask/vertex (independent of par state)
            unsigned em_n = (unsigned)s->nbm[base + 4 + sub] & EMASK;
            unsigned ov_n = s->order32[base + 4 + sub];

            // --- branch-free fixed-point find (root entry is a fixed point:
            //     par[r].low == r, so p <- par[p.low] converges and stays) ---
            bool active = (em >> sl) & 1u;
            int x0 = (int)(ov & 0xFFFFu) + c_off[sl];
            int xr = active ? x0 : 0;          // inactive lanes chase vertex 0
            unsigned p0 = par[xr];
            unsigned p1 = par[p0 & 0xFFFFu];
            unsigned p2 = par[p1 & 0xFFFFu];
            unsigned p3 = par[p2 & 0xFFFFu];
            bool deep = active && ((p3 & 0xFFFFu) != (p2 & 0xFFFFu));
            if (__any_sync(FULL, deep)) {      // rare: depth > 3
                if (deep) {
                    for (;;) {
                        unsigned nx = par[p3 & 0xFFFFu];
                        if ((nx & 0xFFFFu) == (p3 & 0xFFFFu)) { p3 = nx; break; }
                        p3 = nx;
                    }
                }
            }
            par[active ? x0 : NN] = p3;        // full path compression
            unsigned cur = active ? p3 : INV;

            bool valid = active;
            // per-sub single-root check, full-warp intrinsics only:
            // lane ok iff all valid lanes of ITS sub share its root AND root
            // predates the batch. Ok sub's merge = {pre-batch root} U {fresh}:
            // root wins, nothing dies, only (v,v) pairs -> just a join.
            unsigned vmask = __ballot_sync(FULL, valid);
            unsigned grp = __match_any_sync(FULL, cur);
            bool okl = !valid || ((((grp | ~vmask) & submask) == submask) &&
                                  ((cur >> 16) < (unsigned)base));
            unsigned badl = __ballot_sync(FULL, !okl);
            if (badl == 0u) {
                unsigned fa = valid ? (ov & 0xFFFFu) : (unsigned)NN;
                par[fa] = cur;   // sub-uniform value; benign race within sub
            } else {
                // ---- bad-subs-only fix-up ----
                // 1) ok subs join immediately (exact: joins never kill roots;
                //    eligibility guarantees rank ordering is respected)
                unsigned fa = (okl && valid) ? (ov & 0xFFFFu) : (unsigned)NN;
                par[fa] = cur;
                __syncwarp();
                // 2) bad lanes with an in-batch-born root: one re-read redirects
                //    to the pre-batch root if that vertex joined (join stores the
                //    full packed root); unchanged otherwise (self entry).
                if (!okl && valid && (cur >> 16) >= (unsigned)base)
                    cur = par[cur & 0xFFFFu];
                unsigned pvall = ((unsigned)(base + sub) << 16) | (ov & 0xFFFFu);
                unsigned pv0 = __shfl_sync(FULL, pvall, 0);
                unsigned pv1 = __shfl_sync(FULL, pvall, 8);
                unsigned pv2 = __shfl_sync(FULL, pvall, 16);
                unsigned pv3 = __shfl_sync(FULL, pvall, 24);
                // 3) warp-uniform loop over bad subs only (ascending)
                unsigned bsub = 0u;
#pragma unroll
                for (int j = 0; j < 4; j++)
                    if ((badl >> (j << 3)) & 0xFFu) bsub |= 1u << j;
                while (bsub) {
                    int j = __ffs(bsub) - 1;
                    bsub &= bsub - 1;
                    unsigned pvj = (j < 2) ? (j == 0 ? pv0 : pv1) : (j == 2 ? pv2 : pv3);
                    unsigned grp2 = __match_any_sync(FULL, cur);
                    bool valid2 = (cur != INV);
                    bool inj = (sub == j);
                    unsigned wjj = __reduce_min_sync(FULL, (valid2 && inj) ? cur : INV);
                    bool anyv = (wjj != INV);
                    bool deadval = inj && valid2 && (cur != wjj);
                    unsigned dmask = __ballot_sync(FULL, deadval);
                    bool leader = deadval && ((grp2 & dmask & lmlt) == 0u);
                    // branchless stores via dummy slots (no BSSY/BSYNC)
                    unsigned slot = leader ? (cur & 0xFFFFu) : (unsigned)NN;
                    unsigned bp = deadval ? (cur >> 16) : 0u;
                    int lbv = (int)(s->order32[bp] & 0xFFFFu);
                    unsigned vj = pvj & 0xFFFFu;
                    float Bv, Dv;
                    if (DIR == 0) { Bv = s->vals[lbv]; Dv = s->vals[vj]; }
                    else          { Bv = s->vals[vj];  Dv = s->vals[lbv]; }
                    s->spBD[slot] = make_float2(Bv, Dv);
                    par[slot] = wjj;                       // loser root -> winner
                    unsigned fa2 = (anyv && lane == 0) ? vj : (unsigned)(NN + 1);
                    par[fa2] = wjj;                        // fresh vertex joins winner
                    // stale fix (registers only)
                    if (sub > j && valid2) {
                        bool stale = ((grp2 & dmask) != 0u) || (anyv && cur == pvj);
                        if (stale) cur = wjj;
                    }
                }
            }
            __syncwarp();
            em = em_n;
            ov = ov_n;
        }
    }
    __syncthreads();

    // ---- fused landscape top-K: 32 t-values, warp per t ----
    int K = g ? 3 : 2;
    float start = g ? 1.0f : 0.0f;
    int fbase = m * 320 + (g ? 128 : 0);
    for (int ti = warp; ti < 32; ti += 8) {
        float t = start + 7.0f * (float)ti / 31.0f;
        float a0 = -1.f, a1 = -1.f, a2 = -1.f;
        for (int j = lane; j < NN; j += 32) {
            float2 bd = s->spBD[j];
            float tent = fmaxf(fminf(t - bd.x, bd.y - t), 0.f);
            if (tent > a2) {
                if (tent > a0)      { a2 = a1; a1 = a0; a0 = tent; }
                else if (tent > a1) { a2 = a1; a1 = tent; }
                else                { a2 = tent; }
            }
        }
        for (int kk = 0; kk < K; kk++) {
            float w = a0;
#pragma unroll
            for (int off = 16; off; off >>= 1) w = fmaxf(w, __shfl_xor_sync(0xFFFFFFFFu, w, off));
            unsigned bal = __ballot_sync(0xFFFFFFFFu, a0 == w);
            int src = __ffs(bal) - 1;
            if (lane == src) { a0 = a1; a1 = a2; a2 = -1.f; }
            if (lane == 0) g_feats[fbase + (DIR * K + kk) * 32 + ti] = w;
        }
    }
}

__global__ void pairs_kernel() {
    __shared__ SmemC smc;
    int task = blockIdx.x;
    int dir = task & 1;
    int g = (task >> 1) & 1;
    int m = task >> 2;
    if (dir == 0) pairs_body<0>(&smc, g, m);
    else          pairs_body<1>(&smc, g, m);
}

// ---------------------------------------------------------------------------
// Kernel D: tiny MLP. Block per image, 512 threads, warp-per-unit dots.
// ---------------------------------------------------------------------------
__global__ void mlp_kernel(const float* __restrict__ wg1, const float* __restrict__ bg1,
                           const float* __restrict__ wg2, const float* __restrict__ bg2,
                           const float* __restrict__ wfc, const float* __restrict__ bfc,
                           float* __restrict__ out) {
    int m = blockIdx.x;
    __shared__ float sx[64];
    int tid = threadIdx.x;
    int lane = tid & 31, w = tid >> 5;   // 16 warps
    const float* feats = g_feats + m * 320;

#pragma unroll
    for (int i = 0; i < 2; i++) {
        int u = w * 2 + i;
        float a = 0.f;
#pragma unroll
        for (int c = lane; c < 128; c += 32) a += feats[c] * wg1[u * 128 + c];
#pragma unroll
        for (int off = 16; off; off >>= 1) a += __shfl_xor_sync(0xFFFFFFFFu, a, off);
        if (lane == 0) sx[u] = fmaxf(a + bg1[u], 0.f);
    }
#pragma unroll
    for (int i = 0; i < 2; i++) {
        int u = w * 2 + i;
        float a = 0.f;
#pragma unroll
        for (int c = lane; c < 192; c += 32) a += feats[128 + c] * wg2[u * 192 + c];
#pragma unroll
        for (int off = 16; off; off >>= 1) a += __shfl_xor_sync(0xFFFFFFFFu, a, off);
        if (lane == 0) sx[32 + u] = fmaxf(a + bg2[u], 0.f);
    }
    __syncthreads();
    if (tid < 10) {
        float a = bfc[tid];
#pragma unroll
        for (int c = 0; c < 64; c++) a += sx[c] * wfc[tid * 64 + c];
        out[m * 10 + tid] = a;
    }
}

// ---------------------------------------------------------------------------
extern "C" void kernel_launch(void* const* d_in, const int* in_sizes, int n_in,
                              void* d_out, int out_size) {
    const float* x   = (const float*)d_in[0];
    const float* wg1 = (const float*)d_in[1];
    const float* bg1 = (const float*)d_in[2];
    const float* wg2 = (const float*)d_in[3];
    const float* bg2 = (const float*)d_in[4];
    const float* wfc = (const float*)d_in[5];
    const float* bfc = (const float*)d_in[6];
    float* out = (float*)d_out;
    int B = in_sizes[0] / NN;
    if (B > MAXB) B = MAXB;

    build_sort_table_kernel<<<NN, 256>>>();
    dtm_kernel<<<dim3(B, 4), 256>>>(x);
    pairs_kernel<<<B * 4, 256>>>();
    mlp_kernel<<<B, 512>>>(wg1, bg1, wg2, bg2, wfc, bfc, out);
}